// round 14
// baseline (speedup 1.0000x reference)
#include <cuda_runtime.h>
#include <cuda_bf16.h>
#include <cstdint>

#define BATCH_ 8192
#define DIM_   768
#define DICT_  32768
#define TOPK_  32
#define CAND   64

// Plain bf16 filter GEMM (refine makes the final result exact): K = 768
#define K2      768
#define TM      128
#define TN      128
#define BK      32
#define NCH     (K2 / BK)          // 24
#define ASTRIDE 80                 // 64B row + 16B pad: conflict-free ldmatrix
#define A_STAGE (TM * ASTRIDE)     // 10240
#define STAGE_BYTES (2 * A_STAGE)  // 20480
#define STAGES  4
#define SMEM_GEMM (STAGES * STAGE_BYTES)   // 81920

// topk smem layout: row (64KB) + hist (2048 u32 = 8KB) + list (1024 u16 = 2KB)
#define NBKT    2048
#define LCAP    1024
#define SMEM_TOPK (DICT_ * 2 + NBKT * 4 + LCAP * 2)   // 75776

// ---------------------------------------------------------------------------
// Device scratch (allocation-free rule: __device__ globals)
// ---------------------------------------------------------------------------
__device__ __nv_bfloat16 g_XA[(size_t)BATCH_ * K2];    // bf16(X)
__device__ __nv_bfloat16 g_WB[(size_t)DICT_  * K2];    // bf16(W_enc)
__device__ __nv_bfloat16 g_Z [(size_t)BATCH_ * DICT_]; // approx z (bf16)
__device__ float g_WdT[(size_t)DICT_ * DIM_];          // W_dec transposed
__device__ int   g_cand[BATCH_ * CAND];                // approx top-64 indices
__device__ float g_vals[BATCH_ * TOPK_];
__device__ int   g_idx [BATCH_ * TOPK_];

// ---------------------------------------------------------------------------
// PTX helpers (sm_80+ baseline only — NO tcgen05: harness targets sm_103)
// ---------------------------------------------------------------------------
__device__ __forceinline__ uint32_t smem_u32(const void* p) {
    return (uint32_t)__cvta_generic_to_shared(p);
}

__device__ __forceinline__ void cp_async16(uint32_t dst, const void* src) {
    asm volatile("cp.async.cg.shared.global [%0], [%1], 16;"
                 :: "r"(dst), "l"(src) : "memory");
}

__device__ __forceinline__ void ldsm_x4(uint32_t r[4], uint32_t addr) {
    asm volatile("ldmatrix.sync.aligned.m8n8.x4.shared.b16 {%0,%1,%2,%3}, [%4];"
                 : "=r"(r[0]), "=r"(r[1]), "=r"(r[2]), "=r"(r[3]) : "r"(addr));
}

__device__ __forceinline__ void mma16816(float c[4], const uint32_t a[4],
                                         const uint32_t b[2]) {
    asm volatile(
        "mma.sync.aligned.m16n8k16.row.col.f32.bf16.bf16.f32 "
        "{%0,%1,%2,%3}, {%4,%5,%6,%7}, {%8,%9}, {%0,%1,%2,%3};"
        : "+f"(c[0]), "+f"(c[1]), "+f"(c[2]), "+f"(c[3])
        : "r"(a[0]), "r"(a[1]), "r"(a[2]), "r"(a[3]), "r"(b[0]), "r"(b[1]));
}

// ---------------------------------------------------------------------------
// fp32 -> bf16 conversions (vectorized)
// ---------------------------------------------------------------------------
__global__ __launch_bounds__(256) void cvt_x(const float* __restrict__ X) {
    int i = blockIdx.x * 256 + threadIdx.x;
    if (i >= BATCH_ * DIM_ / 4) return;
    float4 v = reinterpret_cast<const float4*>(X)[i];
    reinterpret_cast<__nv_bfloat162*>(g_XA)[i*2]   = __float22bfloat162_rn(make_float2(v.x, v.y));
    reinterpret_cast<__nv_bfloat162*>(g_XA)[i*2+1] = __float22bfloat162_rn(make_float2(v.z, v.w));
}

__global__ __launch_bounds__(256) void cvt_w(const float* __restrict__ W) {
    int i = blockIdx.x * 256 + threadIdx.x;
    if (i >= DICT_ * DIM_ / 4) return;
    float4 v = reinterpret_cast<const float4*>(W)[i];
    reinterpret_cast<__nv_bfloat162*>(g_WB)[i*2]   = __float22bfloat162_rn(make_float2(v.x, v.y));
    reinterpret_cast<__nv_bfloat162*>(g_WB)[i*2+1] = __float22bfloat162_rn(make_float2(v.z, v.w));
}

// ---------------------------------------------------------------------------
// HMMA filter GEMM: Z[m,n] = bf16( sum_k XA[m,k]*WB[n,k] + bias[n] )
// 128x128 CTA tile, BK=32, 8 warps (64x32 warp tiles), cp.async 4-slot ring.
// (R8-proven configuration: 2 CTAs/SM, tensor/smem co-bound.)
// ---------------------------------------------------------------------------
__device__ __forceinline__ void load_stage_g(uint32_t sbase, int slot, int k0,
                                             int m0, int n0, int tid) {
    uint32_t sA = sbase + slot * STAGE_BYTES;
    uint32_t sB = sA + A_STAGE;
    const __nv_bfloat16* Ag = g_XA + (size_t)m0 * K2 + k0;
    const __nv_bfloat16* Bg = g_WB + (size_t)n0 * K2 + k0;
    const int lrow = tid >> 2;       // 0..63
    const int lch  = tid & 3;        // 16B chunk within 64B row
    #pragma unroll
    for (int it = 0; it < 2; it++) {
        int row = lrow + it * 64;
        cp_async16(sA + row * ASTRIDE + lch * 16, Ag + (size_t)row * K2 + lch * 8);
        cp_async16(sB + row * ASTRIDE + lch * 16, Bg + (size_t)row * K2 + lch * 8);
    }
}

__global__ __launch_bounds__(256, 2) void encode_gemm_mma(
    const float* __restrict__ bias)
{
    extern __shared__ char smem[];
    const uint32_t sbase = smem_u32(smem);
    const int tid  = threadIdx.x;
    const int lane = tid & 31;
    const int wid  = tid >> 5;
    const int m0 = blockIdx.x * TM;
    const int n0 = blockIdx.y * TN;
    const int wm = (wid & 1) * 64;
    const int wn = (wid >> 1) * 32;

    float acc[4][4][4];
    #pragma unroll
    for (int mi = 0; mi < 4; mi++)
        #pragma unroll
        for (int ni = 0; ni < 4; ni++)
            #pragma unroll
            for (int r = 0; r < 4; r++) acc[mi][ni][r] = 0.f;

    #pragma unroll
    for (int s = 0; s < 3; s++) {
        load_stage_g(sbase, s, s * BK, m0, n0, tid);
        asm volatile("cp.async.commit_group;" ::: "memory");
    }

    for (int i = 0; i < NCH; i++) {
        asm volatile("cp.async.wait_group 2;" ::: "memory");
        __syncthreads();

        if (i + 3 < NCH)
            load_stage_g(sbase, (i + 3) & 3, (i + 3) * BK, m0, n0, tid);
        asm volatile("cp.async.commit_group;" ::: "memory");

        const uint32_t sA = sbase + (i & 3) * STAGE_BYTES;
        const uint32_t sB = sA + A_STAGE;
        const int g = lane >> 3;

        #pragma unroll
        for (int ks = 0; ks < 2; ks++) {
            uint32_t a[4][4], b[2][4];
            #pragma unroll
            for (int mi = 0; mi < 4; mi++)
                ldsm_x4(a[mi], sA + (wm + mi * 16 + (lane & 15)) * ASTRIDE
                               + ks * 32 + (lane >> 4) * 16);
            #pragma unroll
            for (int nj = 0; nj < 2; nj++)
                ldsm_x4(b[nj], sB + (wn + nj * 16 + (g >> 1) * 8 + (lane & 7)) * ASTRIDE
                               + ks * 32 + (g & 1) * 16);
            #pragma unroll
            for (int mi = 0; mi < 4; mi++)
                #pragma unroll
                for (int ni = 0; ni < 4; ni++)
                    mma16816(acc[mi][ni], a[mi], &b[ni >> 1][(ni & 1) * 2]);
        }
    }

    #pragma unroll
    for (int mi = 0; mi < 4; mi++) {
        int r0 = m0 + wm + mi * 16 + (lane >> 2);
        #pragma unroll
        for (int ni = 0; ni < 4; ni++) {
            int col = n0 + wn + ni * 8 + (lane & 3) * 2;
            float2 bv = *reinterpret_cast<const float2*>(bias + col);
            __nv_bfloat162 v0 = __float22bfloat162_rn(
                make_float2(acc[mi][ni][0] + bv.x, acc[mi][ni][1] + bv.y));
            __nv_bfloat162 v1 = __float22bfloat162_rn(
                make_float2(acc[mi][ni][2] + bv.x, acc[mi][ni][3] + bv.y));
            *reinterpret_cast<__nv_bfloat162*>(g_Z + (size_t)r0 * DICT_ + col)       = v0;
            *reinterpret_cast<__nv_bfloat162*>(g_Z + (size_t)(r0 + 8) * DICT_ + col) = v1;
        }
    }
}

// ---------------------------------------------------------------------------
// Candidate selection on bf16 z: top-CAND indices per row. Also zeroes this
// row of the encoded output (refine scatters the 32 exact values afterwards).
//
// TWO full scans (was three):
//   scan1: 2048-bucket histogram of key16>>5 (sign+8exp+2mant) -> boundary
//          bucket b + residual keq. Boundary bucket expected ~135 elems.
//   scan2: emit bucket>b directly; collect bucket==b indices into L[LCAP].
//   phase3: exact low-5-bit radix over the tiny list (== R10 semantics:
//          exact top-64 by bf16 value, arbitrary among exact bf16 ties).
// Capacity: hist[b] known exactly after scan1; if > LCAP (statistically
// impossible for this data, 135 expected vs 1024 cap) fall back to
// first-keq-of-bucket (still a valid arbitrary tie policy at bucket level).
// ---------------------------------------------------------------------------
__device__ __forceinline__ unsigned key16(unsigned h) {
    return h ^ ((h & 0x8000u) ? 0xFFFFu : 0x8000u);
}

__global__ __launch_bounds__(256) void topk_cand(float* __restrict__ enc)
{
    extern __shared__ char dsm[];
    unsigned short* srow16 = reinterpret_cast<unsigned short*>(dsm);          // 64KB
    unsigned*       hist   = reinterpret_cast<unsigned*>(dsm + DICT_ * 2);    // 8KB
    unsigned short* L      = reinterpret_cast<unsigned short*>(dsm + DICT_ * 2 + NBKT * 4); // 2KB

    const int row = blockIdx.x;
    const int tid = threadIdx.x;

    // Stage row (uint4 = 8 bf16 per load)
    {
        const uint4* z4 = reinterpret_cast<const uint4*>(g_Z + (size_t)row * DICT_);
        uint4* s4 = reinterpret_cast<uint4*>(srow16);
        for (int i = tid; i < DICT_ / 8; i += 256) s4[i] = z4[i];
    }
    // Fused zeroing of this row of the encoded output
    {
        float4 zero = make_float4(0.f, 0.f, 0.f, 0.f);
        float4* e4 = reinterpret_cast<float4*>(enc + (size_t)row * DICT_);
        for (int i = tid; i < DICT_ / 4; i += 256) e4[i] = zero;
    }

    __shared__ unsigned csum[256];
    __shared__ unsigned hist2[32];
    __shared__ int s_b, s_k, s_b2, s_k2, nslot, eq, eq2;

    if (tid == 0) { nslot = 0; eq = 0; eq2 = 0; }
    #pragma unroll
    for (int j = 0; j < NBKT / 256; j++) hist[tid + j * 256] = 0;
    if (tid < 32) hist2[tid] = 0;
    __syncthreads();

    // scan1: 2048-bucket histogram (8 elems per uint4 read)
    for (int i = tid; i < DICT_ / 8; i += 256) {
        uint4 v = reinterpret_cast<uint4*>(srow16)[i];
        atomicAdd(&hist[key16(v.x & 0xFFFFu) >> 5], 1u);
        atomicAdd(&hist[key16(v.x >> 16)     >> 5], 1u);
        atomicAdd(&hist[key16(v.y & 0xFFFFu) >> 5], 1u);
        atomicAdd(&hist[key16(v.y >> 16)     >> 5], 1u);
        atomicAdd(&hist[key16(v.z & 0xFFFFu) >> 5], 1u);
        atomicAdd(&hist[key16(v.z >> 16)     >> 5], 1u);
        atomicAdd(&hist[key16(v.w & 0xFFFFu) >> 5], 1u);
        atomicAdd(&hist[key16(v.w >> 16)     >> 5], 1u);
    }
    __syncthreads();

    // boundary find: chunk sums (8 buckets/thread) then serial over 256+8
    {
        unsigned s = 0;
        #pragma unroll
        for (int j = 0; j < 8; j++) s += hist[tid * 8 + j];
        csum[tid] = s;
    }
    __syncthreads();
    if (tid == 0) {
        int kk = CAND, c = 255;
        for (;; c--) { int s = (int)csum[c]; if (s >= kk) break; kk -= s; }
        int b = c * 8 + 7;
        for (;; b--) { int s = (int)hist[b]; if (s >= kk) break; kk -= s; }
        s_b = b; s_k = kk;
    }
    __syncthreads();
    const unsigned bkt = (unsigned)s_b;
    const int keq = s_k;                    // needed from boundary bucket
    const int bpop = (int)hist[bkt];        // exact boundary-bucket population

    // scan2: emit > bucket, collect == bucket
    for (int i = tid; i < DICT_ / 8; i += 256) {
        uint4 v = reinterpret_cast<uint4*>(srow16)[i];
        unsigned w[4] = {v.x, v.y, v.z, v.w};
        #pragma unroll
        for (int j = 0; j < 4; j++) {
            #pragma unroll
            for (int h = 0; h < 2; h++) {
                unsigned k = key16(h ? (w[j] >> 16) : (w[j] & 0xFFFFu)) >> 5;
                if (k >= bkt) {
                    int idx = i * 8 + j * 2 + h;
                    if (k > bkt) {
                        int s = atomicAdd(&nslot, 1);
                        g_cand[row * CAND + s] = idx;
                    } else {
                        int e = atomicAdd(&eq, 1);
                        if (e < LCAP) L[e] = (unsigned short)idx;
                    }
                }
            }
        }
    }
    __syncthreads();

    if (bpop <= LCAP) {
        // exact low-5-bit refinement over the tiny list
        const int ec = eq;
        for (int i = tid; i < ec; i += 256)
            atomicAdd(&hist2[key16(srow16[L[i]]) & 31u], 1u);
        __syncthreads();
        if (tid == 0) {
            int kk = keq, b = 31;
            for (;; b--) { int s = (int)hist2[b]; if (s >= kk) break; kk -= s; }
            s_b2 = b; s_k2 = kk;
        }
        __syncthreads();
        const unsigned blo = (unsigned)s_b2;
        const int keq2 = s_k2;
        for (int i = tid; i < ec; i += 256) {
            int idx = L[i];
            unsigned lo = key16(srow16[idx]) & 31u;
            if (lo > blo) {
                int s = atomicAdd(&nslot, 1);
                g_cand[row * CAND + s] = idx;
            } else if (lo == blo) {
                int e = atomicAdd(&eq2, 1);
                if (e < keq2) {
                    int s = atomicAdd(&nslot, 1);
                    g_cand[row * CAND + s] = idx;
                }
            }
        }
    } else {
        // pathological overflow (degenerate ties): first keq of the bucket
        for (int i = tid; i < keq; i += 256) {
            int s = atomicAdd(&nslot, 1);
            g_cand[row * CAND + s] = L[i];
        }
    }
}

// ---------------------------------------------------------------------------
// Refine: exact fp32 recompute of the CAND candidates, exact top-32 with
// first-index tie-break, scatter into enc + decode buffers.
// ---------------------------------------------------------------------------
__device__ __forceinline__ unsigned key_of(float f) {
    unsigned u = __float_as_uint(f);
    return u ^ ((u & 0x80000000u) ? 0xFFFFFFFFu : 0x80000000u);
}

__device__ __forceinline__ unsigned long long sel_key(float v, int idx) {
    return ((unsigned long long)key_of(v) << 32) | (unsigned)(0x7FFFFFFF - idx);
}

__global__ __launch_bounds__(256) void refine_kernel(
    const float* __restrict__ X, const float* __restrict__ W_enc,
    const float* __restrict__ b_enc, float* __restrict__ enc)
{
    const int row = blockIdx.x;
    const int tid = threadIdx.x;
    const int w = tid >> 5, lane = tid & 31;
    __shared__ float sx[DIM_];
    __shared__ float cv[CAND];
    __shared__ int   ci[CAND];

    for (int i = tid; i < DIM_ / 4; i += 256)
        reinterpret_cast<float4*>(sx)[i] =
            reinterpret_cast<const float4*>(X + (size_t)row * DIM_)[i];
    if (tid < CAND) ci[tid] = g_cand[row * CAND + tid];
    __syncthreads();

    for (int c = w; c < CAND; c += 8) {
        const float* wr = W_enc + (size_t)ci[c] * DIM_;
        float s = 0.f;
        #pragma unroll
        for (int j = lane * 4; j < DIM_; j += 128) {
            float4 a = *reinterpret_cast<const float4*>(sx + j);
            float4 b = *reinterpret_cast<const float4*>(wr + j);
            s = fmaf(a.x, b.x, s); s = fmaf(a.y, b.y, s);
            s = fmaf(a.z, b.z, s); s = fmaf(a.w, b.w, s);
        }
        #pragma unroll
        for (int o = 16; o; o >>= 1) s += __shfl_xor_sync(0xFFFFFFFFu, s, o);
        if (lane == 0) cv[c] = s + b_enc[ci[c]];
    }
    __syncthreads();

    if (w == 0) {
        unsigned long long ka = sel_key(cv[lane],      ci[lane]);
        unsigned long long kb = sel_key(cv[lane + 32], ci[lane + 32]);
        for (int s = 0; s < TOPK_; s++) {
            unsigned long long m = ka > kb ? ka : kb;
            #pragma unroll
            for (int o = 16; o; o >>= 1) {
                unsigned long long t = __shfl_xor_sync(0xFFFFFFFFu, m, o);
                if (t > m) m = t;
            }
            if (ka == m) {
                int idx = ci[lane]; float v = cv[lane];
                enc[(size_t)row * DICT_ + idx] = v;
                g_vals[row * TOPK_ + s] = v;
                g_idx [row * TOPK_ + s] = idx;
                ka = 0ull;
            } else if (kb == m) {
                int idx = ci[lane + 32]; float v = cv[lane + 32];
                enc[(size_t)row * DICT_ + idx] = v;
                g_vals[row * TOPK_ + s] = v;
                g_idx [row * TOPK_ + s] = idx;
                kb = 0ull;
            }
        }
    }
}

// ---------------------------------------------------------------------------
// W_dec [DIM, DICT] -> g_WdT [DICT, DIM]
// ---------------------------------------------------------------------------
__global__ void transpose_wdec(const float* __restrict__ Wd)
{
    __shared__ float tile[32][33];
    int bx = blockIdx.x * 32;
    int by = blockIdx.y * 32;
    int tx = threadIdx.x, ty = threadIdx.y;
    #pragma unroll
    for (int j = 0; j < 32; j += 8)
        tile[ty + j][tx] = Wd[(size_t)(by + ty + j) * DICT_ + bx + tx];
    __syncthreads();
    #pragma unroll
    for (int j = 0; j < 32; j += 8)
        g_WdT[(size_t)(bx + ty + j) * DIM_ + by + tx] = tile[tx][ty + j];
}

// ---------------------------------------------------------------------------
// Decode + loss
// ---------------------------------------------------------------------------
__global__ __launch_bounds__(256) void decode_kernel(
    const float* __restrict__ X, const float* __restrict__ b_dec,
    float* __restrict__ rec, float* __restrict__ loss)
{
    const int row = blockIdx.x;
    const int tid = threadIdx.x;
    __shared__ float sv[TOPK_];
    __shared__ int   si[TOPK_];
    if (tid < TOPK_) { sv[tid] = g_vals[row * TOPK_ + tid];
                       si[tid] = g_idx [row * TOPK_ + tid]; }
    __syncthreads();

    float acc[3];
    #pragma unroll
    for (int j = 0; j < 3; j++) acc[j] = b_dec[tid + j * 256];

    for (int kk = 0; kk < TOPK_; kk++) {
        const float* w = g_WdT + (size_t)si[kk] * DIM_;
        float v = sv[kk];
        #pragma unroll
        for (int j = 0; j < 3; j++)
            acc[j] = fmaf(v, w[tid + j * 256], acc[j]);
    }

    float err = 0.f;
    #pragma unroll
    for (int j = 0; j < 3; j++) {
        int d = tid + j * 256;
        float r = acc[j];
        rec[(size_t)row * DIM_ + d] = r;
        float diff = r - X[(size_t)row * DIM_ + d];
        err = fmaf(diff, diff, err);
    }
    #pragma unroll
    for (int o = 16; o; o >>= 1) err += __shfl_xor_sync(0xFFFFFFFFu, err, o);
    __shared__ float ws[8];
    if ((tid & 31) == 0) ws[tid >> 5] = err;
    __syncthreads();
    if (tid < 8) {
        float e = ws[tid];
        #pragma unroll
        for (int o = 4; o; o >>= 1) e += __shfl_xor_sync(0xFFu, e, o);
        if (tid == 0) atomicAdd(loss, e * (1.0f / BATCH_));
    }
}

__global__ void zero_loss(float* loss) { if (threadIdx.x == 0) *loss = 0.f; }

// ---------------------------------------------------------------------------
// kernel_launch
// ---------------------------------------------------------------------------
extern "C" void kernel_launch(void* const* d_in, const int* in_sizes, int n_in,
                              void* d_out, int out_size)
{
    const float* X     = (const float*)d_in[0];
    const float* W_enc = (const float*)d_in[1];
    const float* b_enc = (const float*)d_in[2];
    const float* W_dec = (const float*)d_in[3];
    const float* b_dec = (const float*)d_in[4];

    float* out  = (float*)d_out;
    float* rec  = out;
    float* enc  = out + (size_t)BATCH_ * DIM_;
    float* loss = enc + (size_t)BATCH_ * DICT_;

    cudaFuncSetAttribute(topk_cand,
                         cudaFuncAttributeMaxDynamicSharedMemorySize,
                         SMEM_TOPK);
    cudaFuncSetAttribute(encode_gemm_mma,
                         cudaFuncAttributeMaxDynamicSharedMemorySize,
                         SMEM_GEMM);

    cvt_x<<<(BATCH_ * DIM_ / 4 + 255) / 256, 256>>>(X);
    cvt_w<<<(DICT_ * DIM_ / 4 + 255) / 256, 256>>>(W_enc);

    // grid.x = M tiles (fast-varying) so a wave of CTAs shares B tiles in L2
    dim3 gg(BATCH_ / TM, DICT_ / TN);
    encode_gemm_mma<<<gg, 256, SMEM_GEMM>>>(b_enc);

    topk_cand<<<BATCH_, 256, SMEM_TOPK>>>(enc);
    refine_kernel<<<BATCH_, 256>>>(X, W_enc, b_enc, enc);
    transpose_wdec<<<dim3(DICT_ / 32, DIM_ / 32), dim3(32, 8)>>>(W_dec);
    zero_loss<<<1, 32>>>(loss);
    decode_kernel<<<BATCH_, 256>>>(X, b_dec, rec, loss);
}

// round 16
// speedup vs baseline: 1.1341x; 1.1341x over previous
#include <cuda_runtime.h>
#include <cuda_bf16.h>
#include <cstdint>

#define BATCH_ 8192
#define DIM_   768
#define DICT_  32768
#define TOPK_  32
#define CAND   64

// Plain bf16 filter GEMM (refine makes the final result exact): K = 768
#define K2      768
#define TM      128
#define TN      128
#define BK      32
#define NCH     (K2 / BK)          // 24
#define ASTRIDE 80                 // 64B row + 16B pad: conflict-free ldmatrix
#define A_STAGE (TM * ASTRIDE)     // 10240
#define STAGE_BYTES (2 * A_STAGE)  // 20480
#define STAGES  4
#define SMEM_GEMM (STAGES * STAGE_BYTES)   // 81920

// topk: NO row staging (row is L2-resident between the two scans).
// smem = hist (2048 u32 = 8KB) + list (1024 u32 = 4KB) -> 8 CTAs/SM.
#define NBKT    2048
#define LCAP    1024

// ---------------------------------------------------------------------------
// Device scratch (allocation-free rule: __device__ globals)
// ---------------------------------------------------------------------------
__device__ __nv_bfloat16 g_XA[(size_t)BATCH_ * K2];    // bf16(X)
__device__ __nv_bfloat16 g_WB[(size_t)DICT_  * K2];    // bf16(W_enc)
__device__ __nv_bfloat16 g_Z [(size_t)BATCH_ * DICT_]; // approx z (bf16)
__device__ float g_WdT[(size_t)DICT_ * DIM_];          // W_dec transposed
__device__ int   g_cand[BATCH_ * CAND];                // approx top-64 indices
__device__ float g_vals[BATCH_ * TOPK_];
__device__ int   g_idx [BATCH_ * TOPK_];

// ---------------------------------------------------------------------------
// PTX helpers (sm_80+ baseline only — NO tcgen05: harness targets sm_103)
// ---------------------------------------------------------------------------
__device__ __forceinline__ uint32_t smem_u32(const void* p) {
    return (uint32_t)__cvta_generic_to_shared(p);
}

__device__ __forceinline__ void cp_async16(uint32_t dst, const void* src) {
    asm volatile("cp.async.cg.shared.global [%0], [%1], 16;"
                 :: "r"(dst), "l"(src) : "memory");
}

__device__ __forceinline__ void ldsm_x4(uint32_t r[4], uint32_t addr) {
    asm volatile("ldmatrix.sync.aligned.m8n8.x4.shared.b16 {%0,%1,%2,%3}, [%4];"
                 : "=r"(r[0]), "=r"(r[1]), "=r"(r[2]), "=r"(r[3]) : "r"(addr));
}

__device__ __forceinline__ void mma16816(float c[4], const uint32_t a[4],
                                         const uint32_t b[2]) {
    asm volatile(
        "mma.sync.aligned.m16n8k16.row.col.f32.bf16.bf16.f32 "
        "{%0,%1,%2,%3}, {%4,%5,%6,%7}, {%8,%9}, {%0,%1,%2,%3};"
        : "+f"(c[0]), "+f"(c[1]), "+f"(c[2]), "+f"(c[3])
        : "r"(a[0]), "r"(a[1]), "r"(a[2]), "r"(a[3]), "r"(b[0]), "r"(b[1]));
}

// ---------------------------------------------------------------------------
// fp32 -> bf16 conversions (vectorized)
// ---------------------------------------------------------------------------
__global__ __launch_bounds__(256) void cvt_x(const float* __restrict__ X) {
    int i = blockIdx.x * 256 + threadIdx.x;
    if (i >= BATCH_ * DIM_ / 4) return;
    float4 v = reinterpret_cast<const float4*>(X)[i];
    reinterpret_cast<__nv_bfloat162*>(g_XA)[i*2]   = __float22bfloat162_rn(make_float2(v.x, v.y));
    reinterpret_cast<__nv_bfloat162*>(g_XA)[i*2+1] = __float22bfloat162_rn(make_float2(v.z, v.w));
}

__global__ __launch_bounds__(256) void cvt_w(const float* __restrict__ W) {
    int i = blockIdx.x * 256 + threadIdx.x;
    if (i >= DICT_ * DIM_ / 4) return;
    float4 v = reinterpret_cast<const float4*>(W)[i];
    reinterpret_cast<__nv_bfloat162*>(g_WB)[i*2]   = __float22bfloat162_rn(make_float2(v.x, v.y));
    reinterpret_cast<__nv_bfloat162*>(g_WB)[i*2+1] = __float22bfloat162_rn(make_float2(v.z, v.w));
}

// ---------------------------------------------------------------------------
// HMMA filter GEMM: Z[m,n] = bf16( sum_k XA[m,k]*WB[n,k] + bias[n] )
// 128x128 CTA tile, BK=32, 8 warps (64x32 warp tiles), cp.async 4-slot ring.
// (R8-proven configuration: 2 CTAs/SM, tensor/smem co-bound.)
// ---------------------------------------------------------------------------
__device__ __forceinline__ void load_stage_g(uint32_t sbase, int slot, int k0,
                                             int m0, int n0, int tid) {
    uint32_t sA = sbase + slot * STAGE_BYTES;
    uint32_t sB = sA + A_STAGE;
    const __nv_bfloat16* Ag = g_XA + (size_t)m0 * K2 + k0;
    const __nv_bfloat16* Bg = g_WB + (size_t)n0 * K2 + k0;
    const int lrow = tid >> 2;       // 0..63
    const int lch  = tid & 3;        // 16B chunk within 64B row
    #pragma unroll
    for (int it = 0; it < 2; it++) {
        int row = lrow + it * 64;
        cp_async16(sA + row * ASTRIDE + lch * 16, Ag + (size_t)row * K2 + lch * 8);
        cp_async16(sB + row * ASTRIDE + lch * 16, Bg + (size_t)row * K2 + lch * 8);
    }
}

__global__ __launch_bounds__(256, 2) void encode_gemm_mma(
    const float* __restrict__ bias)
{
    extern __shared__ char smem[];
    const uint32_t sbase = smem_u32(smem);
    const int tid  = threadIdx.x;
    const int lane = tid & 31;
    const int wid  = tid >> 5;
    const int m0 = blockIdx.x * TM;
    const int n0 = blockIdx.y * TN;
    const int wm = (wid & 1) * 64;
    const int wn = (wid >> 1) * 32;

    float acc[4][4][4];
    #pragma unroll
    for (int mi = 0; mi < 4; mi++)
        #pragma unroll
        for (int ni = 0; ni < 4; ni++)
            #pragma unroll
            for (int r = 0; r < 4; r++) acc[mi][ni][r] = 0.f;

    #pragma unroll
    for (int s = 0; s < 3; s++) {
        load_stage_g(sbase, s, s * BK, m0, n0, tid);
        asm volatile("cp.async.commit_group;" ::: "memory");
    }

    for (int i = 0; i < NCH; i++) {
        asm volatile("cp.async.wait_group 2;" ::: "memory");
        __syncthreads();

        if (i + 3 < NCH)
            load_stage_g(sbase, (i + 3) & 3, (i + 3) * BK, m0, n0, tid);
        asm volatile("cp.async.commit_group;" ::: "memory");

        const uint32_t sA = sbase + (i & 3) * STAGE_BYTES;
        const uint32_t sB = sA + A_STAGE;
        const int g = lane >> 3;

        #pragma unroll
        for (int ks = 0; ks < 2; ks++) {
            uint32_t a[4][4], b[2][4];
            #pragma unroll
            for (int mi = 0; mi < 4; mi++)
                ldsm_x4(a[mi], sA + (wm + mi * 16 + (lane & 15)) * ASTRIDE
                               + ks * 32 + (lane >> 4) * 16);
            #pragma unroll
            for (int nj = 0; nj < 2; nj++)
                ldsm_x4(b[nj], sB + (wn + nj * 16 + (g >> 1) * 8 + (lane & 7)) * ASTRIDE
                               + ks * 32 + (g & 1) * 16);
            #pragma unroll
            for (int mi = 0; mi < 4; mi++)
                #pragma unroll
                for (int ni = 0; ni < 4; ni++)
                    mma16816(acc[mi][ni], a[mi], &b[ni >> 1][(ni & 1) * 2]);
        }
    }

    #pragma unroll
    for (int mi = 0; mi < 4; mi++) {
        int r0 = m0 + wm + mi * 16 + (lane >> 2);
        #pragma unroll
        for (int ni = 0; ni < 4; ni++) {
            int col = n0 + wn + ni * 8 + (lane & 3) * 2;
            float2 bv = *reinterpret_cast<const float2*>(bias + col);
            __nv_bfloat162 v0 = __float22bfloat162_rn(
                make_float2(acc[mi][ni][0] + bv.x, acc[mi][ni][1] + bv.y));
            __nv_bfloat162 v1 = __float22bfloat162_rn(
                make_float2(acc[mi][ni][2] + bv.x, acc[mi][ni][3] + bv.y));
            *reinterpret_cast<__nv_bfloat162*>(g_Z + (size_t)r0 * DICT_ + col)       = v0;
            *reinterpret_cast<__nv_bfloat162*>(g_Z + (size_t)(r0 + 8) * DICT_ + col) = v1;
        }
    }
}

// ---------------------------------------------------------------------------
// Candidate selection on bf16 z: top-CAND indices per row. Also zeroes this
// row of the encoded output (refine scatters the 32 exact values afterwards).
//
// NO smem row staging: the 64KB row is read from global twice; the second
// read hits L2 (working set = active CTAs * 64KB << 126MB L2). smem is just
// hist(8KB) + list(4KB) -> 8 CTAs/SM for latency hiding (R14 was 2 CTAs/SM
// and latency-bound at issue=23%).
//   scan1: 2048-bucket histogram of key16>>5 -> boundary bucket + residual.
//   scan2: emit bucket>b; pack (low5key,idx) of bucket==b into L.
//   phase3: exact low-5-bit radix over the tiny list (no row re-read).
// Selection semantics identical to R10/R14 (exact top-64 by bf16 value,
// arbitrary among exact bf16 ties; refine recomputes exactly in fp32).
// ---------------------------------------------------------------------------
__device__ __forceinline__ unsigned key16(unsigned h) {
    return h ^ ((h & 0x8000u) ? 0xFFFFu : 0x8000u);
}

__global__ __launch_bounds__(256) void topk_cand(float* __restrict__ enc)
{
    const int row = blockIdx.x;
    const int tid = threadIdx.x;
    const uint4* z4 = reinterpret_cast<const uint4*>(g_Z + (size_t)row * DICT_);

    __shared__ unsigned hist[NBKT];     // 8KB
    __shared__ unsigned L[LCAP];        // 4KB: (low5key << 16) | idx
    __shared__ unsigned csum[256];
    __shared__ unsigned hist2[32];
    __shared__ int s_b, s_k, s_b2, s_k2, nslot, eq, eq2;

    if (tid == 0) { nslot = 0; eq = 0; eq2 = 0; }
    #pragma unroll
    for (int j = 0; j < NBKT / 256; j++) hist[tid + j * 256] = 0;
    if (tid < 32) hist2[tid] = 0;
    __syncthreads();

    // scan1: 2048-bucket histogram (8 elems per uint4 global read)
    for (int i = tid; i < DICT_ / 8; i += 256) {
        uint4 v = z4[i];
        atomicAdd(&hist[key16(v.x & 0xFFFFu) >> 5], 1u);
        atomicAdd(&hist[key16(v.x >> 16)     >> 5], 1u);
        atomicAdd(&hist[key16(v.y & 0xFFFFu) >> 5], 1u);
        atomicAdd(&hist[key16(v.y >> 16)     >> 5], 1u);
        atomicAdd(&hist[key16(v.z & 0xFFFFu) >> 5], 1u);
        atomicAdd(&hist[key16(v.z >> 16)     >> 5], 1u);
        atomicAdd(&hist[key16(v.w & 0xFFFFu) >> 5], 1u);
        atomicAdd(&hist[key16(v.w >> 16)     >> 5], 1u);
    }
    __syncthreads();

    // boundary find: chunk sums (8 buckets/thread) then serial on thread 0
    {
        unsigned s = 0;
        #pragma unroll
        for (int j = 0; j < 8; j++) s += hist[tid * 8 + j];
        csum[tid] = s;
    }
    __syncthreads();
    if (tid == 0) {
        int kk = CAND, c = 255;
        for (;; c--) { int s = (int)csum[c]; if (s >= kk) break; kk -= s; }
        int b = c * 8 + 7;
        for (;; b--) { int s = (int)hist[b]; if (s >= kk) break; kk -= s; }
        s_b = b; s_k = kk;
    }
    __syncthreads();
    const unsigned bkt = (unsigned)s_b;
    const int keq = s_k;                    // needed from boundary bucket
    const int bpop = (int)hist[bkt];        // exact boundary-bucket population

    // Fused zeroing of this row of the encoded output (write-only; overlaps
    // with scan2's L2 reads)
    {
        float4 zero = make_float4(0.f, 0.f, 0.f, 0.f);
        float4* e4 = reinterpret_cast<float4*>(enc + (size_t)row * DICT_);
        for (int i = tid; i < DICT_ / 4; i += 256) e4[i] = zero;
    }

    // scan2: re-read row (L2-resident); emit > bucket, pack == bucket
    for (int i = tid; i < DICT_ / 8; i += 256) {
        uint4 v = z4[i];
        unsigned w[4] = {v.x, v.y, v.z, v.w};
        #pragma unroll
        for (int j = 0; j < 4; j++) {
            #pragma unroll
            for (int h = 0; h < 2; h++) {
                unsigned k16 = key16(h ? (w[j] >> 16) : (w[j] & 0xFFFFu));
                unsigned k = k16 >> 5;
                if (k >= bkt) {
                    int idx = i * 8 + j * 2 + h;
                    if (k > bkt) {
                        int s = atomicAdd(&nslot, 1);
                        g_cand[row * CAND + s] = idx;
                    } else {
                        int e = atomicAdd(&eq, 1);
                        if (e < LCAP) L[e] = ((k16 & 31u) << 16) | (unsigned)idx;
                    }
                }
            }
        }
    }
    __syncthreads();

    if (bpop <= LCAP) {
        // exact low-5-bit refinement over the tiny list (values packed in L)
        const int ec = eq;
        for (int i = tid; i < ec; i += 256)
            atomicAdd(&hist2[L[i] >> 16], 1u);
        __syncthreads();
        if (tid == 0) {
            int kk = keq, b = 31;
            for (;; b--) { int s = (int)hist2[b]; if (s >= kk) break; kk -= s; }
            s_b2 = b; s_k2 = kk;
        }
        __syncthreads();
        const unsigned blo = (unsigned)s_b2;
        const int keq2 = s_k2;
        for (int i = tid; i < ec; i += 256) {
            unsigned ent = L[i];
            unsigned lo = ent >> 16;
            if (lo > blo) {
                int s = atomicAdd(&nslot, 1);
                g_cand[row * CAND + s] = (int)(ent & 0xFFFFu);
            } else if (lo == blo) {
                int e = atomicAdd(&eq2, 1);
                if (e < keq2) {
                    int s = atomicAdd(&nslot, 1);
                    g_cand[row * CAND + s] = (int)(ent & 0xFFFFu);
                }
            }
        }
    } else {
        // pathological overflow (degenerate ties): first keq of the bucket
        for (int i = tid; i < keq; i += 256) {
            int s = atomicAdd(&nslot, 1);
            g_cand[row * CAND + s] = (int)(L[i] & 0xFFFFu);
        }
    }
}

// ---------------------------------------------------------------------------
// Refine: exact fp32 recompute of the CAND candidates, exact top-32 with
// first-index tie-break, scatter into enc + decode buffers.
// ---------------------------------------------------------------------------
__device__ __forceinline__ unsigned key_of(float f) {
    unsigned u = __float_as_uint(f);
    return u ^ ((u & 0x80000000u) ? 0xFFFFFFFFu : 0x80000000u);
}

__device__ __forceinline__ unsigned long long sel_key(float v, int idx) {
    return ((unsigned long long)key_of(v) << 32) | (unsigned)(0x7FFFFFFF - idx);
}

__global__ __launch_bounds__(256) void refine_kernel(
    const float* __restrict__ X, const float* __restrict__ W_enc,
    const float* __restrict__ b_enc, float* __restrict__ enc)
{
    const int row = blockIdx.x;
    const int tid = threadIdx.x;
    const int w = tid >> 5, lane = tid & 31;
    __shared__ float sx[DIM_];
    __shared__ float cv[CAND];
    __shared__ int   ci[CAND];

    for (int i = tid; i < DIM_ / 4; i += 256)
        reinterpret_cast<float4*>(sx)[i] =
            reinterpret_cast<const float4*>(X + (size_t)row * DIM_)[i];
    if (tid < CAND) ci[tid] = g_cand[row * CAND + tid];
    __syncthreads();

    for (int c = w; c < CAND; c += 8) {
        const float* wr = W_enc + (size_t)ci[c] * DIM_;
        float s = 0.f;
        #pragma unroll
        for (int j = lane * 4; j < DIM_; j += 128) {
            float4 a = *reinterpret_cast<const float4*>(sx + j);
            float4 b = *reinterpret_cast<const float4*>(wr + j);
            s = fmaf(a.x, b.x, s); s = fmaf(a.y, b.y, s);
            s = fmaf(a.z, b.z, s); s = fmaf(a.w, b.w, s);
        }
        #pragma unroll
        for (int o = 16; o; o >>= 1) s += __shfl_xor_sync(0xFFFFFFFFu, s, o);
        if (lane == 0) cv[c] = s + b_enc[ci[c]];
    }
    __syncthreads();

    if (w == 0) {
        unsigned long long ka = sel_key(cv[lane],      ci[lane]);
        unsigned long long kb = sel_key(cv[lane + 32], ci[lane + 32]);
        for (int s = 0; s < TOPK_; s++) {
            unsigned long long m = ka > kb ? ka : kb;
            #pragma unroll
            for (int o = 16; o; o >>= 1) {
                unsigned long long t = __shfl_xor_sync(0xFFFFFFFFu, m, o);
                if (t > m) m = t;
            }
            if (ka == m) {
                int idx = ci[lane]; float v = cv[lane];
                enc[(size_t)row * DICT_ + idx] = v;
                g_vals[row * TOPK_ + s] = v;
                g_idx [row * TOPK_ + s] = idx;
                ka = 0ull;
            } else if (kb == m) {
                int idx = ci[lane + 32]; float v = cv[lane + 32];
                enc[(size_t)row * DICT_ + idx] = v;
                g_vals[row * TOPK_ + s] = v;
                g_idx [row * TOPK_ + s] = idx;
                kb = 0ull;
            }
        }
    }
}

// ---------------------------------------------------------------------------
// W_dec [DIM, DICT] -> g_WdT [DICT, DIM]
// ---------------------------------------------------------------------------
__global__ void transpose_wdec(const float* __restrict__ Wd)
{
    __shared__ float tile[32][33];
    int bx = blockIdx.x * 32;
    int by = blockIdx.y * 32;
    int tx = threadIdx.x, ty = threadIdx.y;
    #pragma unroll
    for (int j = 0; j < 32; j += 8)
        tile[ty + j][tx] = Wd[(size_t)(by + ty + j) * DICT_ + bx + tx];
    __syncthreads();
    #pragma unroll
    for (int j = 0; j < 32; j += 8)
        g_WdT[(size_t)(bx + ty + j) * DIM_ + by + tx] = tile[tx][ty + j];
}

// ---------------------------------------------------------------------------
// Decode + loss
// ---------------------------------------------------------------------------
__global__ __launch_bounds__(256) void decode_kernel(
    const float* __restrict__ X, const float* __restrict__ b_dec,
    float* __restrict__ rec, float* __restrict__ loss)
{
    const int row = blockIdx.x;
    const int tid = threadIdx.x;
    __shared__ float sv[TOPK_];
    __shared__ int   si[TOPK_];
    if (tid < TOPK_) { sv[tid] = g_vals[row * TOPK_ + tid];
                       si[tid] = g_idx [row * TOPK_ + tid]; }
    __syncthreads();

    float acc[3];
    #pragma unroll
    for (int j = 0; j < 3; j++) acc[j] = b_dec[tid + j * 256];

    for (int kk = 0; kk < TOPK_; kk++) {
        const float* w = g_WdT + (size_t)si[kk] * DIM_;
        float v = sv[kk];
        #pragma unroll
        for (int j = 0; j < 3; j++)
            acc[j] = fmaf(v, w[tid + j * 256], acc[j]);
    }

    float err = 0.f;
    #pragma unroll
    for (int j = 0; j < 3; j++) {
        int d = tid + j * 256;
        float r = acc[j];
        rec[(size_t)row * DIM_ + d] = r;
        float diff = r - X[(size_t)row * DIM_ + d];
        err = fmaf(diff, diff, err);
    }
    #pragma unroll
    for (int o = 16; o; o >>= 1) err += __shfl_xor_sync(0xFFFFFFFFu, err, o);
    __shared__ float ws[8];
    if ((tid & 31) == 0) ws[tid >> 5] = err;
    __syncthreads();
    if (tid < 8) {
        float e = ws[tid];
        #pragma unroll
        for (int o = 4; o; o >>= 1) e += __shfl_xor_sync(0xFFu, e, o);
        if (tid == 0) atomicAdd(loss, e * (1.0f / BATCH_));
    }
}

__global__ void zero_loss(float* loss) { if (threadIdx.x == 0) *loss = 0.f; }

// ---------------------------------------------------------------------------
// kernel_launch
// ---------------------------------------------------------------------------
extern "C" void kernel_launch(void* const* d_in, const int* in_sizes, int n_in,
                              void* d_out, int out_size)
{
    const float* X     = (const float*)d_in[0];
    const float* W_enc = (const float*)d_in[1];
    const float* b_enc = (const float*)d_in[2];
    const float* W_dec = (const float*)d_in[3];
    const float* b_dec = (const float*)d_in[4];

    float* out  = (float*)d_out;
    float* rec  = out;
    float* enc  = out + (size_t)BATCH_ * DIM_;
    float* loss = enc + (size_t)BATCH_ * DICT_;

    cudaFuncSetAttribute(encode_gemm_mma,
                         cudaFuncAttributeMaxDynamicSharedMemorySize,
                         SMEM_GEMM);

    cvt_x<<<(BATCH_ * DIM_ / 4 + 255) / 256, 256>>>(X);
    cvt_w<<<(DICT_ * DIM_ / 4 + 255) / 256, 256>>>(W_enc);

    // grid.x = M tiles (fast-varying) so a wave of CTAs shares B tiles in L2
    dim3 gg(BATCH_ / TM, DICT_ / TN);
    encode_gemm_mma<<<gg, 256, SMEM_GEMM>>>(b_enc);

    topk_cand<<<BATCH_, 256>>>(enc);
    refine_kernel<<<BATCH_, 256>>>(X, W_enc, b_enc, enc);
    transpose_wdec<<<dim3(DICT_ / 32, DIM_ / 32), dim3(32, 8)>>>(W_dec);
    zero_loss<<<1, 32>>>(loss);
    decode_kernel<<<BATCH_, 256>>>(X, b_dec, rec, loss);
}